// round 14
// baseline (speedup 1.0000x reference)
#include <cuda_runtime.h>
#include <cuda_bf16.h>
#include <cstdint>
#include <cstring>
#include <math.h>

// ResBlock: out = x + W2 @ gelu(W1 @ LN(x) + b1) + b2    (N=65536, D=512, fp32)
//
// BASE-PTX mma.sync tensor path (plain sm_103 target: no 'a'-gated tcgen05).
// Numerics: bf16 hi/lo split, C = Ah*Bh + Ah*Bl + Al*Bh, fp32 accumulators.
// R14 = R8 pipeline (six broker timeouts, zero kernel failures; audit clean x3):
// 3-stage cp.async pipeline, 1 sync/chunk, full fragment double-buffering.

using bf16 = __nv_bfloat16;

constexpr int NROWS = 65536;
constexpr int DIM   = 512;
constexpr int BM = 128, BN = 128, BK = 32;
constexpr int NKC = DIM / BK;                 // 16 k-chunks
constexpr int NSTAGE = 3;

// SMEM staging (padded rows -> conflict-free ldmatrix)
constexpr int A_STRIDE = 40;                  // bf16/row (80 B)
constexpr int B_STRIDE = 136;                 // bf16/row (272 B)
constexpr int A_TILE = BM * A_STRIDE * 2;     // 10240 B
constexpr int B_TILE = BK * B_STRIDE * 2;     // 8704 B
constexpr int OFF_AH = 0;
constexpr int OFF_AL = A_TILE;
constexpr int OFF_BH = 2 * A_TILE;
constexpr int OFF_BL = 2 * A_TILE + B_TILE;
constexpr int BUF_B  = 2 * A_TILE + 2 * B_TILE;   // 37888 B per stage
constexpr int SMEM_TOTAL = NSTAGE * BUF_B;        // 113664 B

// ---------------------------------------------------------------------------
// scratch (device globals — allocation-free per harness rules)
// ---------------------------------------------------------------------------
__device__ bf16 g_a1h[(size_t)NROWS * DIM], g_a1l[(size_t)NROWS * DIM];
__device__ bf16 g_g2h[(size_t)NROWS * DIM], g_g2l[(size_t)NROWS * DIM];
__device__ bf16 g_w1h[DIM * DIM], g_w1l[DIM * DIM];   // [k][n], n contiguous
__device__ bf16 g_w2h[DIM * DIM], g_w2l[DIM * DIM];

// ---------------------------------------------------------------------------
// helpers (all base PTX: cp.async sm_80, ldmatrix sm_75, mma.sync bf16 sm_80)
// ---------------------------------------------------------------------------
__device__ __forceinline__ uint32_t smem_u32(const void* p) {
    uint32_t a;
    asm("{ .reg .u64 t; cvta.to.shared.u64 t, %1; cvt.u32.u64 %0, t; }" : "=r"(a) : "l"(p));
    return a;
}
#define CP_ASYNC16(sm, gm) \
    asm volatile("cp.async.cg.shared.global [%0], [%1], 16;" :: "r"(sm), "l"(gm))
#define CP_COMMIT() asm volatile("cp.async.commit_group;" ::: "memory")
#define CP_WAIT1()  asm volatile("cp.async.wait_group 1;" ::: "memory")
#define CP_WAIT0()  asm volatile("cp.async.wait_group 0;" ::: "memory")

__device__ __forceinline__ void ldsm_x4(uint32_t* r, uint32_t a) {
    asm volatile("ldmatrix.sync.aligned.m8n8.x4.shared.b16 {%0,%1,%2,%3}, [%4];"
        : "=r"(r[0]), "=r"(r[1]), "=r"(r[2]), "=r"(r[3]) : "r"(a));
}
__device__ __forceinline__ void ldsm_x4_t(uint32_t* r, uint32_t a) {
    asm volatile("ldmatrix.sync.aligned.m8n8.x4.trans.shared.b16 {%0,%1,%2,%3}, [%4];"
        : "=r"(r[0]), "=r"(r[1]), "=r"(r[2]), "=r"(r[3]) : "r"(a));
}
__device__ __forceinline__ void mma_bf16(float* c, const uint32_t* a, const uint32_t* b) {
    asm volatile(
        "mma.sync.aligned.m16n8k16.row.col.f32.bf16.bf16.f32 "
        "{%0,%1,%2,%3}, {%4,%5,%6,%7}, {%8,%9}, {%0,%1,%2,%3};"
        : "+f"(c[0]), "+f"(c[1]), "+f"(c[2]), "+f"(c[3])
        : "r"(a[0]), "r"(a[1]), "r"(a[2]), "r"(a[3]), "r"(b[0]), "r"(b[1]));
}

__device__ __forceinline__ float gelu_exact(float v) {
    return 0.5f * v * (1.0f + erff(v * 0.70710678118654752f));
}
__device__ __forceinline__ uint32_t pack2f(float a, float b) {
    __nv_bfloat162 t = __floats2bfloat162_rn(a, b);
    uint32_t u; memcpy(&u, &t, 4); return u;
}
__device__ __forceinline__ uint32_t pack2(bf16 a, bf16 b) {
    __nv_bfloat162 t = __halves2bfloat162(a, b);
    uint32_t u; memcpy(&u, &t, 4); return u;
}

// ---------------------------------------------------------------------------
// Kernel 1: fused LN + bf16 hi/lo split. One warp per row.
// ---------------------------------------------------------------------------
__global__ void __launch_bounds__(256) ln_convert_kernel(
    const float* __restrict__ x, const float* __restrict__ gamma,
    const float* __restrict__ beta, bf16* __restrict__ ahi, bf16* __restrict__ alo)
{
    const int warp = threadIdx.x >> 5, lane = threadIdx.x & 31;
    const int row  = (blockIdx.x << 3) + warp;

    const float4* xr = reinterpret_cast<const float4*>(x + (size_t)row * DIM);
    float4 v[4];
    float s = 0.f, ss = 0.f;
#pragma unroll
    for (int i = 0; i < 4; i++) {
        v[i] = xr[lane + (i << 5)];
        s  += v[i].x + v[i].y + v[i].z + v[i].w;
        ss += v[i].x * v[i].x + v[i].y * v[i].y + v[i].z * v[i].z + v[i].w * v[i].w;
    }
#pragma unroll
    for (int o = 16; o > 0; o >>= 1) {
        s  += __shfl_xor_sync(0xffffffffu, s,  o);
        ss += __shfl_xor_sync(0xffffffffu, ss, o);
    }
    const float mu = s * (1.0f / DIM);
    const float r  = rsqrtf(ss * (1.0f / DIM) - mu * mu + 1e-5f);

    const float4* g4 = reinterpret_cast<const float4*>(gamma);
    const float4* b4 = reinterpret_cast<const float4*>(beta);
#pragma unroll
    for (int i = 0; i < 4; i++) {
        const int c = lane + (i << 5);
        const float4 g = g4[c], b = b4[c];
        float o0 = (v[i].x - mu) * r * g.x + b.x;
        float o1 = (v[i].y - mu) * r * g.y + b.y;
        float o2 = (v[i].z - mu) * r * g.z + b.z;
        float o3 = (v[i].w - mu) * r * g.w + b.w;
        bf16 h0 = __float2bfloat16(o0), h1 = __float2bfloat16(o1);
        bf16 h2 = __float2bfloat16(o2), h3 = __float2bfloat16(o3);
        uint2 ph = { pack2(h0, h1), pack2(h2, h3) };
        uint2 pl = { pack2f(o0 - __bfloat162float(h0), o1 - __bfloat162float(h1)),
                     pack2f(o2 - __bfloat162float(h2), o3 - __bfloat162float(h3)) };
        *reinterpret_cast<uint2*>(ahi + (size_t)row * DIM + 4 * c) = ph;
        *reinterpret_cast<uint2*>(alo + (size_t)row * DIM + 4 * c) = pl;
    }
}

// ---------------------------------------------------------------------------
// Kernel 2: W1,W2 -> hi/lo bf16 split, layout preserved ([k][n], n contig).
// ---------------------------------------------------------------------------
__global__ void __launch_bounds__(256) wsplit_kernel(
    const float* __restrict__ W1, bf16* __restrict__ t1h, bf16* __restrict__ t1l,
    const float* __restrict__ W2, bf16* __restrict__ t2h, bf16* __restrict__ t2l)
{
    const int i4 = blockIdx.x * 256 + threadIdx.x;       // 0..131071, 4 elems each
    const bool second = i4 >= 65536;
    const float* W = second ? W2 : W1;
    bf16* th = second ? t2h : t1h;
    bf16* tl = second ? t2l : t1l;
    const int o = (second ? i4 - 65536 : i4) * 4;

    const float4 v = *reinterpret_cast<const float4*>(W + o);
    bf16 h0 = __float2bfloat16(v.x), h1 = __float2bfloat16(v.y);
    bf16 h2 = __float2bfloat16(v.z), h3 = __float2bfloat16(v.w);
    uint2 ph = { pack2(h0, h1), pack2(h2, h3) };
    uint2 pl = { pack2f(v.x - __bfloat162float(h0), v.y - __bfloat162float(h1)),
                 pack2f(v.z - __bfloat162float(h2), v.w - __bfloat162float(h3)) };
    *reinterpret_cast<uint2*>(th + o) = ph;
    *reinterpret_cast<uint2*>(tl + o) = pl;
}

// ---------------------------------------------------------------------------
// Stage one BK chunk of Ah/Al ([row][k], pre-offset by bm) and Bh/Bl
// ([k][n], pre-offset by bn) into padded SMEM via cp.async. 8x16B per thread.
// ---------------------------------------------------------------------------
__device__ __forceinline__ void stage_chunk(
    uint32_t sbuf, const bf16* __restrict__ a_h, const bf16* __restrict__ a_l,
    const bf16* __restrict__ b_h, const bf16* __restrict__ b_l, int kc, int tid)
{
#pragma unroll
    for (int i = 0; i < 2; i++) {                 // A: 512 xfers of 16B per array
        const int x = tid * 2 + i;
        const int row = x >> 2, c = x & 3;        // 4 x 16B per 64B row-slice
        const uint32_t so = (uint32_t)(row * (A_STRIDE * 2) + c * 16);
        const size_t go = (size_t)row * DIM + kc * BK + c * 8;
        CP_ASYNC16(sbuf + OFF_AH + so, a_h + go);
        CP_ASYNC16(sbuf + OFF_AL + so, a_l + go);
    }
#pragma unroll
    for (int i = 0; i < 2; i++) {                 // B: 512 xfers of 16B per array
        const int x = tid * 2 + i;
        const int k = x >> 4, c = x & 15;         // 16 x 16B per 256B row-slice
        const uint32_t so = (uint32_t)(k * (B_STRIDE * 2) + c * 16);
        const size_t go = (size_t)(kc * BK + k) * DIM + c * 8;
        CP_ASYNC16(sbuf + OFF_BH + so, b_h + go);
        CP_ASYNC16(sbuf + OFF_BL + so, b_l + go);
    }
}

// Fragment set for one k16 step of the 64x32 warp tile (hi+lo operands).
struct Frags {
    uint32_t ah[4][4], al[4][4], bh[4][2], bl[4][2];
};

__device__ __forceinline__ void ld_frags(Frags& f, uint32_t buf, int ks,
                                         int wm, int wn, int lane)
{
#pragma unroll
    for (int mi = 0; mi < 4; mi++) {
        const uint32_t ad = buf + OFF_AH +
            (uint32_t)((wm + mi * 16 + (lane & 15)) * (A_STRIDE * 2) +
                       ks * 32 + (lane >> 4) * 16);
        ldsm_x4(f.ah[mi], ad);
        ldsm_x4(f.al[mi], ad + (OFF_AL - OFF_AH));
    }
#pragma unroll
    for (int j = 0; j < 2; j++) {     // each trans-ldmatrix covers 2 n-tiles
        const uint32_t bd = buf + OFF_BH +
            (uint32_t)((ks * 16 + (lane & 15)) * (B_STRIDE * 2) +
                       (wn + j * 16) * 2 + (lane >> 4) * 16);
        uint32_t t[4];
        ldsm_x4_t(t, bd);
        f.bh[2*j][0] = t[0]; f.bh[2*j][1] = t[1];
        f.bh[2*j+1][0] = t[2]; f.bh[2*j+1][1] = t[3];
        ldsm_x4_t(t, bd + (OFF_BL - OFF_BH));
        f.bl[2*j][0] = t[0]; f.bl[2*j][1] = t[1];
        f.bl[2*j+1][0] = t[2]; f.bl[2*j+1][1] = t[3];
    }
}

__device__ __forceinline__ void mma_all(float acc[4][4][4], const Frags& f) {
#pragma unroll
    for (int mi = 0; mi < 4; mi++)
#pragma unroll
        for (int nj = 0; nj < 4; nj++) {
            mma_bf16(acc[mi][nj], f.ah[mi], f.bh[nj]);   // Ah*Bh
            mma_bf16(acc[mi][nj], f.ah[mi], f.bl[nj]);   // Ah*Bl
            mma_bf16(acc[mi][nj], f.al[mi], f.bh[nj]);   // Al*Bh
        }
}

// ---------------------------------------------------------------------------
// GEMM via mma.sync m16n8k16 bf16, 3-product split, fp32 accum.
// CTA: 128x128 tile, 8 warps in 2(m) x 4(n), warp tile 64x32.
// 3-stage cp.async pipeline; 1 __syncthreads per chunk; frag double-buffer
// (set f0 = ks0 of current/next chunk, set f1 = ks1 of current chunk).
// ---------------------------------------------------------------------------
template <bool GELU>
__global__ void __launch_bounds__(256, 1) gemm_mma_kernel(
    const bf16* __restrict__ Ah, const bf16* __restrict__ Al,
    const bf16* __restrict__ Bh, const bf16* __restrict__ Bl,
    const float* __restrict__ bias, const float* __restrict__ resid,
    float* __restrict__ outF, bf16* __restrict__ outHi, bf16* __restrict__ outLo)
{
    extern __shared__ char smem[];
    const uint32_t sb = smem_u32(smem);
    const int tid = threadIdx.x, wid = tid >> 5, lane = tid & 31;
    const int bm = blockIdx.y * BM, bn = blockIdx.x * BN;
    const int wm = (wid & 1) * 64;        // warp m-offset within CTA tile
    const int wn = (wid >> 1) * 32;       // warp n-offset

    const bf16* a_h = Ah + (size_t)bm * DIM;
    const bf16* a_l = Al + (size_t)bm * DIM;
    const bf16* b_h = Bh + bn;
    const bf16* b_l = Bl + bn;

    float acc[4][4][4];
#pragma unroll
    for (int i = 0; i < 4; i++)
#pragma unroll
        for (int j = 0; j < 4; j++)
#pragma unroll
            for (int e = 0; e < 4; e++) acc[i][j][e] = 0.f;

    // prologue: 2-chunk prefetch lead
    stage_chunk(sb, a_h, a_l, b_h, b_l, 0, tid);
    CP_COMMIT();
    stage_chunk(sb + BUF_B, a_h, a_l, b_h, b_l, 1, tid);
    CP_COMMIT();
    CP_WAIT1();                      // stage 0 landed
    __syncthreads();

    Frags f0, f1;
    ld_frags(f0, sb, 0, wm, wn, lane);     // chunk 0, ks0

    for (int kc = 0; kc < NKC; kc++) {
        const uint32_t cur = sb + (uint32_t)((kc % NSTAGE) * BUF_B);
        if (kc + 2 < NKC) {                // prefetch chunk kc+2 (2-chunk lead)
            stage_chunk(sb + (uint32_t)(((kc + 2) % NSTAGE) * BUF_B),
                        a_h, a_l, b_h, b_l, kc + 2, tid);
            CP_COMMIT();
        }
        ld_frags(f1, cur, 1, wm, wn, lane);    // ks1 frags (stage already visible)
        mma_all(acc, f0);                       // ks0 MMAs

        if (kc + 1 < NKC) {
            if (kc + 2 < NKC) CP_WAIT1(); else CP_WAIT0();
            __syncthreads();                    // stage kc+1 visible to all warps
            ld_frags(f0, sb + (uint32_t)(((kc + 1) % NSTAGE) * BUF_B),
                     0, wm, wn, lane);          // next chunk ks0, hides behind ks1 MMAs
        }
        mma_all(acc, f1);                       // ks1 MMAs
    }

    // ---- epilogue: direct global stores from fragments ----
    const int r0 = bm + wm + (lane >> 2);
    const int c0 = bn + wn + (lane & 3) * 2;
#pragma unroll
    for (int nj = 0; nj < 4; nj++) {
        const int col = c0 + nj * 8;
        const float2 bb = *reinterpret_cast<const float2*>(bias + col);
#pragma unroll
        for (int mi = 0; mi < 4; mi++) {
#pragma unroll
            for (int h = 0; h < 2; h++) {
                const int row = r0 + mi * 16 + h * 8;
                float o0 = acc[mi][nj][2 * h + 0] + bb.x;
                float o1 = acc[mi][nj][2 * h + 1] + bb.y;
                if (GELU) {
                    o0 = gelu_exact(o0);
                    o1 = gelu_exact(o1);
                    const bf16 h0 = __float2bfloat16(o0), h1 = __float2bfloat16(o1);
                    *reinterpret_cast<uint32_t*>(outHi + (size_t)row * DIM + col) =
                        pack2(h0, h1);
                    *reinterpret_cast<uint32_t*>(outLo + (size_t)row * DIM + col) =
                        pack2f(o0 - __bfloat162float(h0), o1 - __bfloat162float(h1));
                } else {
                    const float2 rr = *reinterpret_cast<const float2*>(
                        resid + (size_t)row * DIM + col);
                    float2 o = make_float2(o0 + rr.x, o1 + rr.y);
                    *reinterpret_cast<float2*>(outF + (size_t)row * DIM + col) = o;
                }
            }
        }
    }
}

// ---------------------------------------------------------------------------
extern "C" void kernel_launch(void* const* d_in, const int* in_sizes, int n_in,
                              void* d_out, int out_size)
{
    const float* x     = (const float*)d_in[0];
    const float* gamma = (const float*)d_in[1];
    const float* beta  = (const float*)d_in[2];
    const float* W1    = (const float*)d_in[3];
    const float* b1    = (const float*)d_in[4];
    const float* W2    = (const float*)d_in[5];
    const float* b2    = (const float*)d_in[6];
    float* out = (float*)d_out;

    bf16 *a1h, *a1l, *g2h, *g2l, *w1h, *w1l, *w2h, *w2l;
    cudaGetSymbolAddress((void**)&a1h, g_a1h);   // address queries, not allocations
    cudaGetSymbolAddress((void**)&a1l, g_a1l);
    cudaGetSymbolAddress((void**)&g2h, g_g2h);
    cudaGetSymbolAddress((void**)&g2l, g_g2l);
    cudaGetSymbolAddress((void**)&w1h, g_w1h);
    cudaGetSymbolAddress((void**)&w1l, g_w1l);
    cudaGetSymbolAddress((void**)&w2h, g_w2h);
    cudaGetSymbolAddress((void**)&w2l, g_w2l);

    cudaFuncSetAttribute(gemm_mma_kernel<true>,
                         cudaFuncAttributeMaxDynamicSharedMemorySize, SMEM_TOTAL);
    cudaFuncSetAttribute(gemm_mma_kernel<false>,
                         cudaFuncAttributeMaxDynamicSharedMemorySize, SMEM_TOTAL);

    ln_convert_kernel<<<NROWS / 8, 256>>>(x, gamma, beta, a1h, a1l);
    wsplit_kernel<<<512, 256>>>(W1, w1h, w1l, W2, w2h, w2l);

    dim3 grid(DIM / BN, NROWS / BM);             // (4, 512)
    gemm_mma_kernel<true ><<<grid, 256, SMEM_TOTAL>>>(a1h, a1l, w1h, w1l, b1,
                                                      nullptr, nullptr, g2h, g2l);
    gemm_mma_kernel<false><<<grid, 256, SMEM_TOTAL>>>(g2h, g2l, w2h, w2l, b2,
                                                      x, out, nullptr, nullptr);
}

// round 15
// speedup vs baseline: 1.1342x; 1.1342x over previous
#include <cuda_runtime.h>
#include <cuda_bf16.h>
#include <cstdint>
#include <cstring>
#include <math.h>

// ResBlock: out = x + W2 @ gelu(W1 @ LN(x) + b1) + b2    (N=65536, D=512, fp32)
//
// BASE-PTX mma.sync tensor path. bf16 hi/lo split: C = Ah*Bh + Ah*Bl + Al*Bh.
// R15: 512 threads (16 warps, 4/SMSP) with 32x32 warp tiles — measured evidence
// (R7 and R14 both ~45% tensor despite opposite pipeline structures) says the
// cap is warp-level latency hiding, not barriers/staging. Product-major MMA
// order (independent consecutive HMMAs); single frag set (TLP replaces ILP).

using bf16 = __nv_bfloat16;

constexpr int NROWS = 65536;
constexpr int DIM   = 512;
constexpr int BM = 128, BN = 128, BK = 32;
constexpr int NKC = DIM / BK;                 // 16 k-chunks
constexpr int NSTAGE = 3;
constexpr int THREADS = 512;

// SMEM staging (padded rows -> conflict-free ldmatrix)
constexpr int A_STRIDE = 40;                  // bf16/row (80 B)
constexpr int B_STRIDE = 136;                 // bf16/row (272 B)
constexpr int A_TILE = BM * A_STRIDE * 2;     // 10240 B
constexpr int B_TILE = BK * B_STRIDE * 2;     // 8704 B
constexpr int OFF_AH = 0;
constexpr int OFF_AL = A_TILE;
constexpr int OFF_BH = 2 * A_TILE;
constexpr int OFF_BL = 2 * A_TILE + B_TILE;
constexpr int BUF_B  = 2 * A_TILE + 2 * B_TILE;   // 37888 B per stage
constexpr int SMEM_TOTAL = NSTAGE * BUF_B;        // 113664 B

// ---------------------------------------------------------------------------
// scratch (device globals — allocation-free per harness rules)
// ---------------------------------------------------------------------------
__device__ bf16 g_a1h[(size_t)NROWS * DIM], g_a1l[(size_t)NROWS * DIM];
__device__ bf16 g_g2h[(size_t)NROWS * DIM], g_g2l[(size_t)NROWS * DIM];
__device__ bf16 g_w1h[DIM * DIM], g_w1l[DIM * DIM];   // [k][n], n contiguous
__device__ bf16 g_w2h[DIM * DIM], g_w2l[DIM * DIM];

// ---------------------------------------------------------------------------
// helpers (all base PTX: cp.async sm_80, ldmatrix sm_75, mma.sync bf16 sm_80)
// ---------------------------------------------------------------------------
__device__ __forceinline__ uint32_t smem_u32(const void* p) {
    uint32_t a;
    asm("{ .reg .u64 t; cvta.to.shared.u64 t, %1; cvt.u32.u64 %0, t; }" : "=r"(a) : "l"(p));
    return a;
}
#define CP_ASYNC16(sm, gm) \
    asm volatile("cp.async.cg.shared.global [%0], [%1], 16;" :: "r"(sm), "l"(gm))
#define CP_COMMIT() asm volatile("cp.async.commit_group;" ::: "memory")
#define CP_WAIT1()  asm volatile("cp.async.wait_group 1;" ::: "memory")
#define CP_WAIT0()  asm volatile("cp.async.wait_group 0;" ::: "memory")

__device__ __forceinline__ void ldsm_x4(uint32_t* r, uint32_t a) {
    asm volatile("ldmatrix.sync.aligned.m8n8.x4.shared.b16 {%0,%1,%2,%3}, [%4];"
        : "=r"(r[0]), "=r"(r[1]), "=r"(r[2]), "=r"(r[3]) : "r"(a));
}
__device__ __forceinline__ void ldsm_x4_t(uint32_t* r, uint32_t a) {
    asm volatile("ldmatrix.sync.aligned.m8n8.x4.trans.shared.b16 {%0,%1,%2,%3}, [%4];"
        : "=r"(r[0]), "=r"(r[1]), "=r"(r[2]), "=r"(r[3]) : "r"(a));
}
__device__ __forceinline__ void mma_bf16(float* c, const uint32_t* a, const uint32_t* b) {
    asm volatile(
        "mma.sync.aligned.m16n8k16.row.col.f32.bf16.bf16.f32 "
        "{%0,%1,%2,%3}, {%4,%5,%6,%7}, {%8,%9}, {%0,%1,%2,%3};"
        : "+f"(c[0]), "+f"(c[1]), "+f"(c[2]), "+f"(c[3])
        : "r"(a[0]), "r"(a[1]), "r"(a[2]), "r"(a[3]), "r"(b[0]), "r"(b[1]));
}

__device__ __forceinline__ float gelu_exact(float v) {
    return 0.5f * v * (1.0f + erff(v * 0.70710678118654752f));
}
__device__ __forceinline__ uint32_t pack2f(float a, float b) {
    __nv_bfloat162 t = __floats2bfloat162_rn(a, b);
    uint32_t u; memcpy(&u, &t, 4); return u;
}
__device__ __forceinline__ uint32_t pack2(bf16 a, bf16 b) {
    __nv_bfloat162 t = __halves2bfloat162(a, b);
    uint32_t u; memcpy(&u, &t, 4); return u;
}

// ---------------------------------------------------------------------------
// Kernel 1: fused LN + bf16 hi/lo split. One warp per row.
// ---------------------------------------------------------------------------
__global__ void __launch_bounds__(256) ln_convert_kernel(
    const float* __restrict__ x, const float* __restrict__ gamma,
    const float* __restrict__ beta, bf16* __restrict__ ahi, bf16* __restrict__ alo)
{
    const int warp = threadIdx.x >> 5, lane = threadIdx.x & 31;
    const int row  = (blockIdx.x << 3) + warp;

    const float4* xr = reinterpret_cast<const float4*>(x + (size_t)row * DIM);
    float4 v[4];
    float s = 0.f, ss = 0.f;
#pragma unroll
    for (int i = 0; i < 4; i++) {
        v[i] = xr[lane + (i << 5)];
        s  += v[i].x + v[i].y + v[i].z + v[i].w;
        ss += v[i].x * v[i].x + v[i].y * v[i].y + v[i].z * v[i].z + v[i].w * v[i].w;
    }
#pragma unroll
    for (int o = 16; o > 0; o >>= 1) {
        s  += __shfl_xor_sync(0xffffffffu, s,  o);
        ss += __shfl_xor_sync(0xffffffffu, ss, o);
    }
    const float mu = s * (1.0f / DIM);
    const float r  = rsqrtf(ss * (1.0f / DIM) - mu * mu + 1e-5f);

    const float4* g4 = reinterpret_cast<const float4*>(gamma);
    const float4* b4 = reinterpret_cast<const float4*>(beta);
#pragma unroll
    for (int i = 0; i < 4; i++) {
        const int c = lane + (i << 5);
        const float4 g = g4[c], b = b4[c];
        float o0 = (v[i].x - mu) * r * g.x + b.x;
        float o1 = (v[i].y - mu) * r * g.y + b.y;
        float o2 = (v[i].z - mu) * r * g.z + b.z;
        float o3 = (v[i].w - mu) * r * g.w + b.w;
        bf16 h0 = __float2bfloat16(o0), h1 = __float2bfloat16(o1);
        bf16 h2 = __float2bfloat16(o2), h3 = __float2bfloat16(o3);
        uint2 ph = { pack2(h0, h1), pack2(h2, h3) };
        uint2 pl = { pack2f(o0 - __bfloat162float(h0), o1 - __bfloat162float(h1)),
                     pack2f(o2 - __bfloat162float(h2), o3 - __bfloat162float(h3)) };
        *reinterpret_cast<uint2*>(ahi + (size_t)row * DIM + 4 * c) = ph;
        *reinterpret_cast<uint2*>(alo + (size_t)row * DIM + 4 * c) = pl;
    }
}

// ---------------------------------------------------------------------------
// Kernel 2: W1,W2 -> hi/lo bf16 split, layout preserved ([k][n], n contig).
// ---------------------------------------------------------------------------
__global__ void __launch_bounds__(256) wsplit_kernel(
    const float* __restrict__ W1, bf16* __restrict__ t1h, bf16* __restrict__ t1l,
    const float* __restrict__ W2, bf16* __restrict__ t2h, bf16* __restrict__ t2l)
{
    const int i4 = blockIdx.x * 256 + threadIdx.x;       // 0..131071, 4 elems each
    const bool second = i4 >= 65536;
    const float* W = second ? W2 : W1;
    bf16* th = second ? t2h : t1h;
    bf16* tl = second ? t2l : t1l;
    const int o = (second ? i4 - 65536 : i4) * 4;

    const float4 v = *reinterpret_cast<const float4*>(W + o);
    bf16 h0 = __float2bfloat16(v.x), h1 = __float2bfloat16(v.y);
    bf16 h2 = __float2bfloat16(v.z), h3 = __float2bfloat16(v.w);
    uint2 ph = { pack2(h0, h1), pack2(h2, h3) };
    uint2 pl = { pack2f(v.x - __bfloat162float(h0), v.y - __bfloat162float(h1)),
                 pack2f(v.z - __bfloat162float(h2), v.w - __bfloat162float(h3)) };
    *reinterpret_cast<uint2*>(th + o) = ph;
    *reinterpret_cast<uint2*>(tl + o) = pl;
}

// ---------------------------------------------------------------------------
// Stage one BK chunk of Ah/Al ([row][k], pre-offset by bm) and Bh/Bl
// ([k][n], pre-offset by bn) into padded SMEM via cp.async.
// 512 threads: each thread does ONE 16B xfer per array (4 total).
// ---------------------------------------------------------------------------
__device__ __forceinline__ void stage_chunk(
    uint32_t sbuf, const bf16* __restrict__ a_h, const bf16* __restrict__ a_l,
    const bf16* __restrict__ b_h, const bf16* __restrict__ b_l, int kc, int tid)
{
    {   // A: 512 xfers of 16B per array
        const int row = tid >> 2, c = tid & 3;        // 4 x 16B per 64B row-slice
        const uint32_t so = (uint32_t)(row * (A_STRIDE * 2) + c * 16);
        const size_t go = (size_t)row * DIM + kc * BK + c * 8;
        CP_ASYNC16(sbuf + OFF_AH + so, a_h + go);
        CP_ASYNC16(sbuf + OFF_AL + so, a_l + go);
    }
    {   // B: 512 xfers of 16B per array
        const int k = tid >> 4, c = tid & 15;         // 16 x 16B per 256B row-slice
        const uint32_t so = (uint32_t)(k * (B_STRIDE * 2) + c * 16);
        const size_t go = (size_t)(kc * BK + k) * DIM + c * 8;
        CP_ASYNC16(sbuf + OFF_BH + so, b_h + go);
        CP_ASYNC16(sbuf + OFF_BL + so, b_l + go);
    }
}

// Fragment set for one k16 step of the 32x32 warp tile (hi+lo operands).
struct Frags {
    uint32_t ah[2][4], al[2][4], bh[4][2], bl[4][2];
};

__device__ __forceinline__ void ld_frags(Frags& f, uint32_t buf, int ks,
                                         int wm, int wn, int lane)
{
#pragma unroll
    for (int mi = 0; mi < 2; mi++) {
        const uint32_t ad = buf + OFF_AH +
            (uint32_t)((wm + mi * 16 + (lane & 15)) * (A_STRIDE * 2) +
                       ks * 32 + (lane >> 4) * 16);
        ldsm_x4(f.ah[mi], ad);
        ldsm_x4(f.al[mi], ad + (OFF_AL - OFF_AH));
    }
#pragma unroll
    for (int j = 0; j < 2; j++) {     // each trans-ldmatrix covers 2 n-tiles
        const uint32_t bd = buf + OFF_BH +
            (uint32_t)((ks * 16 + (lane & 15)) * (B_STRIDE * 2) +
                       (wn + j * 16) * 2 + (lane >> 4) * 16);
        uint32_t t[4];
        ldsm_x4_t(t, bd);
        f.bh[2*j][0] = t[0]; f.bh[2*j][1] = t[1];
        f.bh[2*j+1][0] = t[2]; f.bh[2*j+1][1] = t[3];
        ldsm_x4_t(t, bd + (OFF_BL - OFF_BH));
        f.bl[2*j][0] = t[0]; f.bl[2*j][1] = t[1];
        f.bl[2*j+1][0] = t[2]; f.bl[2*j+1][1] = t[3];
    }
}

// Product-major order: consecutive HMMAs hit different accumulators
// (dependency distance 8 instead of 1 -> scheduler can keep the pipe fed).
__device__ __forceinline__ void mma_all(float acc[2][4][4], const Frags& f) {
#pragma unroll
    for (int mi = 0; mi < 2; mi++)
#pragma unroll
        for (int nj = 0; nj < 4; nj++)
            mma_bf16(acc[mi][nj], f.ah[mi], f.bh[nj]);   // Ah*Bh
#pragma unroll
    for (int mi = 0; mi < 2; mi++)
#pragma unroll
        for (int nj = 0; nj < 4; nj++)
            mma_bf16(acc[mi][nj], f.ah[mi], f.bl[nj]);   // Ah*Bl
#pragma unroll
    for (int mi = 0; mi < 2; mi++)
#pragma unroll
        for (int nj = 0; nj < 4; nj++)
            mma_bf16(acc[mi][nj], f.al[mi], f.bh[nj]);   // Al*Bh
}

// ---------------------------------------------------------------------------
// GEMM via mma.sync m16n8k16 bf16, 3-product split, fp32 accum.
// CTA: 128x128 tile, 16 warps in 4(m) x 4(n), warp tile 32x32 (4 warps/SMSP).
// 3-stage cp.async pipeline; 1 __syncthreads per chunk; single frag set.
// ---------------------------------------------------------------------------
template <bool GELU>
__global__ void __launch_bounds__(THREADS, 1) gemm_mma_kernel(
    const bf16* __restrict__ Ah, const bf16* __restrict__ Al,
    const bf16* __restrict__ Bh, const bf16* __restrict__ Bl,
    const float* __restrict__ bias, const float* __restrict__ resid,
    float* __restrict__ outF, bf16* __restrict__ outHi, bf16* __restrict__ outLo)
{
    extern __shared__ char smem[];
    const uint32_t sb = smem_u32(smem);
    const int tid = threadIdx.x, wid = tid >> 5, lane = tid & 31;
    const int bm = blockIdx.y * BM, bn = blockIdx.x * BN;
    const int wm = (wid & 3) * 32;        // warp m-offset within CTA tile
    const int wn = (wid >> 2) * 32;       // warp n-offset

    const bf16* a_h = Ah + (size_t)bm * DIM;
    const bf16* a_l = Al + (size_t)bm * DIM;
    const bf16* b_h = Bh + bn;
    const bf16* b_l = Bl + bn;

    float acc[2][4][4];
#pragma unroll
    for (int i = 0; i < 2; i++)
#pragma unroll
        for (int j = 0; j < 4; j++)
#pragma unroll
            for (int e = 0; e < 4; e++) acc[i][j][e] = 0.f;

    // prologue: 2-chunk prefetch lead
    stage_chunk(sb, a_h, a_l, b_h, b_l, 0, tid);
    CP_COMMIT();
    stage_chunk(sb + BUF_B, a_h, a_l, b_h, b_l, 1, tid);
    CP_COMMIT();
    CP_WAIT1();                      // stage 0 landed
    __syncthreads();

    Frags f;
    for (int kc = 0; kc < NKC; kc++) {
        const uint32_t cur = sb + (uint32_t)((kc % NSTAGE) * BUF_B);
        if (kc + 2 < NKC) {                // prefetch chunk kc+2 (2-chunk lead)
            stage_chunk(sb + (uint32_t)(((kc + 2) % NSTAGE) * BUF_B),
                        a_h, a_l, b_h, b_l, kc + 2, tid);
            CP_COMMIT();
        }
        ld_frags(f, cur, 0, wm, wn, lane);
        mma_all(acc, f);                        // ks0
        ld_frags(f, cur, 1, wm, wn, lane);
        mma_all(acc, f);                        // ks1

        if (kc + 1 < NKC) {
            if (kc + 2 < NKC) CP_WAIT1(); else CP_WAIT0();
            __syncthreads();                    // stage kc+1 visible to all warps
        }
    }

    // ---- epilogue: direct global stores from fragments ----
    const int r0 = bm + wm + (lane >> 2);
    const int c0 = bn + wn + (lane & 3) * 2;
#pragma unroll
    for (int nj = 0; nj < 4; nj++) {
        const int col = c0 + nj * 8;
        const float2 bb = *reinterpret_cast<const float2*>(bias + col);
#pragma unroll
        for (int mi = 0; mi < 2; mi++) {
#pragma unroll
            for (int h = 0; h < 2; h++) {
                const int row = r0 + mi * 16 + h * 8;
                float o0 = acc[mi][nj][2 * h + 0] + bb.x;
                float o1 = acc[mi][nj][2 * h + 1] + bb.y;
                if (GELU) {
                    o0 = gelu_exact(o0);
                    o1 = gelu_exact(o1);
                    const bf16 h0 = __float2bfloat16(o0), h1 = __float2bfloat16(o1);
                    *reinterpret_cast<uint32_t*>(outHi + (size_t)row * DIM + col) =
                        pack2(h0, h1);
                    *reinterpret_cast<uint32_t*>(outLo + (size_t)row * DIM + col) =
                        pack2f(o0 - __bfloat162float(h0), o1 - __bfloat162float(h1));
                } else {
                    const float2 rr = *reinterpret_cast<const float2*>(
                        resid + (size_t)row * DIM + col);
                    float2 o = make_float2(o0 + rr.x, o1 + rr.y);
                    *reinterpret_cast<float2*>(outF + (size_t)row * DIM + col) = o;
                }
            }
        }
    }
}

// ---------------------------------------------------------------------------
extern "C" void kernel_launch(void* const* d_in, const int* in_sizes, int n_in,
                              void* d_out, int out_size)
{
    const float* x     = (const float*)d_in[0];
    const float* gamma = (const float*)d_in[1];
    const float* beta  = (const float*)d_in[2];
    const float* W1    = (const float*)d_in[3];
    const float* b1    = (const float*)d_in[4];
    const float* W2    = (const float*)d_in[5];
    const float* b2    = (const float*)d_in[6];
    float* out = (float*)d_out;

    bf16 *a1h, *a1l, *g2h, *g2l, *w1h, *w1l, *w2h, *w2l;
    cudaGetSymbolAddress((void**)&a1h, g_a1h);   // address queries, not allocations
    cudaGetSymbolAddress((void**)&a1l, g_a1l);
    cudaGetSymbolAddress((void**)&g2h, g_g2h);
    cudaGetSymbolAddress((void**)&g2l, g_g2l);
    cudaGetSymbolAddress((void**)&w1h, g_w1h);
    cudaGetSymbolAddress((void**)&w1l, g_w1l);
    cudaGetSymbolAddress((void**)&w2h, g_w2h);
    cudaGetSymbolAddress((void**)&w2l, g_w2l);

    cudaFuncSetAttribute(gemm_mma_kernel<true>,
                         cudaFuncAttributeMaxDynamicSharedMemorySize, SMEM_TOTAL);
    cudaFuncSetAttribute(gemm_mma_kernel<false>,
                         cudaFuncAttributeMaxDynamicSharedMemorySize, SMEM_TOTAL);

    ln_convert_kernel<<<NROWS / 8, 256>>>(x, gamma, beta, a1h, a1l);
    wsplit_kernel<<<512, 256>>>(W1, w1h, w1l, W2, w2h, w2l);

    dim3 grid(DIM / BN, NROWS / BM);             // (4, 512)
    gemm_mma_kernel<true ><<<grid, THREADS, SMEM_TOTAL>>>(a1h, a1l, w1h, w1l, b1,
                                                          nullptr, nullptr, g2h, g2l);
    gemm_mma_kernel<false><<<grid, THREADS, SMEM_TOTAL>>>(g2h, g2l, w2h, w2l, b2,
                                                          x, out, nullptr, nullptr);
}